// round 15
// baseline (speedup 1.0000x reference)
#include <cuda_runtime.h>
#include <cuda_bf16.h>
#include <math.h>
#include <stdint.h>

#define BATCH 32
#define LSEQ  401
#define NTOK  (BATCH*LSEQ)       // 12832
#define DM    192
#define DI    384
#define DS    16
#define DTR   12
#define XD    44                  // DT_RANK + 2*D_STATE
#define NCLS  1000
#define NCHUNK 8
#define CL    51                  // ceil(401/8)

__device__ __forceinline__ uint32_t smem_to_u32(const void* p) {
    uint32_t a;
    asm("{ .reg .u64 t; cvta.to.shared.u64 t, %1; cvt.u32.u64 %0, t; }"
        : "=r"(a) : "l"(p));
    return a;
}

__device__ __forceinline__ void split_bf16(float x, __nv_bfloat16& h, __nv_bfloat16& l) {
    h = __float2bfloat16(x);
    l = __float2bfloat16(x - __bfloat162float(h));
}

__device__ __forceinline__ void cp_async16(uint32_t dst, const void* src, bool pred) {
    int sz = pred ? 16 : 0;
    asm volatile("cp.async.cg.shared.global [%0], [%1], 16, %2;"
                 :: "r"(dst), "l"(src), "r"(sz));
}
#define CP_COMMIT() asm volatile("cp.async.commit_group;" ::: "memory")
#define CP_WAIT(n)  asm volatile("cp.async.wait_group %0;" :: "n"(n) : "memory")

// ---------------- scratch (device globals; no allocation allowed) -------------
__device__ float g_resid [NTOK*DM];
__device__ float g_xz    [NTOK*2*DI];
__device__ float g_uconv [NTOK*DI];
__device__ float g_xdbl  [NTOK*XD];
__device__ float g_dt    [NTOK*DI];
__device__ float g_cls   [BATCH*DM];
__device__ float g_scanF [BATCH*NCHUNK*DI*DS];
__device__ float g_scanP [BATCH*NCHUNK*DI*DS];
__device__ float g_scanI [BATCH*NCHUNK*DI*DS];

__device__ __nv_bfloat16 g_ah[NTOK*DM],  g_al[NTOK*DM];
__device__ __nv_bfloat16 g_uh[NTOK*DI],  g_ul[NTOK*DI];
__device__ __nv_bfloat16 g_yh[NTOK*DI],  g_yl[NTOK*DI];
__device__ __nv_bfloat16 g_wih[4*768*DM], g_wil[4*768*DM];
__device__ __nv_bfloat16 g_wxh[4*64*DI],  g_wxl[4*64*DI];
__device__ __nv_bfloat16 g_woh[4*DM*DI],  g_wol[4*DM*DI];

// ============ bf16 split-precision tensor-core GEMM (mma.sync/HMMA) ==========
#define LDSM_X4(f, addr) \
    asm volatile("ldmatrix.sync.aligned.m8n8.x4.shared.b16 {%0,%1,%2,%3}, [%4];" \
        : "=r"((f)[0]), "=r"((f)[1]), "=r"((f)[2]), "=r"((f)[3]) : "r"(addr))
#define MMA16816(c, a, b0, b1) \
    asm volatile("mma.sync.aligned.m16n8k16.row.col.f32.bf16.bf16.f32 " \
        "{%0,%1,%2,%3}, {%4,%5,%6,%7}, {%8,%9}, {%0,%1,%2,%3};" \
        : "+f"((c)[0]), "+f"((c)[1]), "+f"((c)[2]), "+f"((c)[3]) \
        : "r"((a)[0]), "r"((a)[1]), "r"((a)[2]), "r"((a)[3]), "r"(b0), "r"(b1))

#define G_ST   15360
#define G_OAH  0
#define G_OAL  5120
#define G_OBH  10240
#define G_OBL  12800
#define GEMM_SMEM_BYTES (2 * G_ST * 2)

// generic 128x64 GEMM (used for xproj): 2-stage cp.async
__global__ void __launch_bounds__(256)
gemm_mma(const __nv_bfloat16* __restrict__ Ah, const __nv_bfloat16* __restrict__ Al,
         const __nv_bfloat16* __restrict__ Bh, const __nv_bfloat16* __restrict__ Bl,
         float* __restrict__ C, int M, int N, int K) {
    extern __shared__ __nv_bfloat16 smbuf[];
    const uint32_t sb = smem_to_u32(smbuf);
    int tid = threadIdx.x, lane = tid & 31, wid = tid >> 5;
    int mw = wid & 3, nw = wid >> 2;
    int m0 = blockIdx.y * 128, n0 = blockIdx.x * 64;

    float acc[2][4][4] = {};
    int sub = lane >> 3, rin = lane & 7;
    int a_row = rin + (sub & 1) * 8;
    int a_col = (sub >> 1) * 8;
    int b_row = rin + (sub >> 1) * 8;
    int b_col = (sub & 1) * 8;

    int ar0 = tid >> 2,  ac0 = (tid & 3) * 8;
    int ar1 = ar0 + 64;
    int br  = tid >> 2,  bc = (tid & 3) * 8;

    auto load_stage = [&](int kc, int s) {
        uint32_t so = (uint32_t)s * G_ST;
        bool v0 = (m0 + ar0 < M);
        bool v1 = (m0 + ar1 < M);
        const __nv_bfloat16* ah0 = Ah + (v0 ? ((size_t)(m0 + ar0) * K + kc * 32 + ac0) : 0);
        const __nv_bfloat16* ah1 = Ah + (v1 ? ((size_t)(m0 + ar1) * K + kc * 32 + ac0) : 0);
        const __nv_bfloat16* al0 = Al + (v0 ? ((size_t)(m0 + ar0) * K + kc * 32 + ac0) : 0);
        const __nv_bfloat16* al1 = Al + (v1 ? ((size_t)(m0 + ar1) * K + kc * 32 + ac0) : 0);
        cp_async16(sb + 2 * (so + G_OAH + ar0 * 40 + ac0), ah0, v0);
        cp_async16(sb + 2 * (so + G_OAH + ar1 * 40 + ac0), ah1, v1);
        cp_async16(sb + 2 * (so + G_OAL + ar0 * 40 + ac0), al0, v0);
        cp_async16(sb + 2 * (so + G_OAL + ar1 * 40 + ac0), al1, v1);
        size_t gb = (size_t)(n0 + br) * K + kc * 32 + bc;
        cp_async16(sb + 2 * (so + G_OBH + br * 40 + bc), Bh + gb, true);
        cp_async16(sb + 2 * (so + G_OBL + br * 40 + bc), Bl + gb, true);
    };

    int nc = K >> 5;
    load_stage(0, 0);
    CP_COMMIT();

    for (int kc = 0; kc < nc; kc++) {
        if (kc + 1 < nc) {
            load_stage(kc + 1, (kc + 1) & 1);
            CP_COMMIT();
            CP_WAIT(1);
        } else {
            CP_WAIT(0);
        }
        __syncthreads();

        uint32_t so = (uint32_t)(kc & 1) * G_ST;
#pragma unroll
        for (int ks = 0; ks < 2; ks++) {
            int kk = ks * 16;
            uint32_t ahf[2][4], alf[2][4], bhf[2][4], blf[2][4];
#pragma unroll
            for (int mt = 0; mt < 2; mt++) {
                uint32_t ro = (mw * 32 + mt * 16 + a_row) * 40 + kk + a_col;
                LDSM_X4(ahf[mt], sb + 2 * (so + G_OAH + ro));
                LDSM_X4(alf[mt], sb + 2 * (so + G_OAL + ro));
            }
#pragma unroll
            for (int np = 0; np < 2; np++) {
                uint32_t ro = (nw * 32 + np * 16 + b_row) * 40 + kk + b_col;
                LDSM_X4(bhf[np], sb + 2 * (so + G_OBH + ro));
                LDSM_X4(blf[np], sb + 2 * (so + G_OBL + ro));
            }
#pragma unroll
            for (int mt = 0; mt < 2; mt++)
#pragma unroll
                for (int nt = 0; nt < 4; nt++) {
                    int hp = nt >> 1, pp = (nt & 1) * 2;
                    MMA16816(acc[mt][nt], ahf[mt], bhf[hp][pp], bhf[hp][pp+1]);
                    MMA16816(acc[mt][nt], ahf[mt], blf[hp][pp], blf[hp][pp+1]);
                    MMA16816(acc[mt][nt], alf[mt], bhf[hp][pp], bhf[hp][pp+1]);
                }
        }
        __syncthreads();
    }

    int g = lane >> 2, t = lane & 3;
#pragma unroll
    for (int mt = 0; mt < 2; mt++)
#pragma unroll
        for (int nt = 0; nt < 4; nt++) {
            int row = m0 + mw * 32 + mt * 16 + g;
            int col = n0 + nw * 32 + nt * 8 + t * 2;
            if (col < N) {
                if (row < M)
                    *(float2*)&C[(size_t)row * N + col] =
                        make_float2(acc[mt][nt][0], acc[mt][nt][1]);
                if (row + 8 < M)
                    *(float2*)&C[(size_t)(row + 8) * N + col] =
                        make_float2(acc[mt][nt][2], acc[mt][nt][3]);
            }
        }
}

// ---- 128x128 tile variant (in_proj only; N multiple of 128), 2-stage --------
#define H_ST   20480
#define H_OAH  0
#define H_OAL  5120
#define H_OBH  10240
#define H_OBL  15360
#define GEMM128_SMEM_BYTES (2 * H_ST * 2)

__global__ void __launch_bounds__(256)
gemm_mma128(const __nv_bfloat16* __restrict__ Ah, const __nv_bfloat16* __restrict__ Al,
            const __nv_bfloat16* __restrict__ Bh, const __nv_bfloat16* __restrict__ Bl,
            float* __restrict__ C, int M, int N, int K) {
    extern __shared__ __nv_bfloat16 smbuf[];
    const uint32_t sb = smem_to_u32(smbuf);
    int tid = threadIdx.x, lane = tid & 31, wid = tid >> 5;
    int mw = wid & 3, nw = wid >> 2;
    int m0 = blockIdx.y * 128, n0 = blockIdx.x * 128;

    float acc[2][8][4] = {};
    int sub = lane >> 3, rin = lane & 7;
    int a_row = rin + (sub & 1) * 8;
    int a_col = (sub >> 1) * 8;
    int b_row = rin + (sub >> 1) * 8;
    int b_col = (sub & 1) * 8;

    int r0_ = tid >> 2,  c0_ = (tid & 3) * 8;
    int r1_ = r0_ + 64;

    auto load_stage = [&](int kc, int s) {
        uint32_t so = (uint32_t)s * H_ST;
        bool v0 = (m0 + r0_ < M);
        bool v1 = (m0 + r1_ < M);
        const __nv_bfloat16* ah0 = Ah + (v0 ? ((size_t)(m0 + r0_) * K + kc * 32 + c0_) : 0);
        const __nv_bfloat16* ah1 = Ah + (v1 ? ((size_t)(m0 + r1_) * K + kc * 32 + c0_) : 0);
        const __nv_bfloat16* al0 = Al + (v0 ? ((size_t)(m0 + r0_) * K + kc * 32 + c0_) : 0);
        const __nv_bfloat16* al1 = Al + (v1 ? ((size_t)(m0 + r1_) * K + kc * 32 + c0_) : 0);
        cp_async16(sb + 2 * (so + H_OAH + r0_ * 40 + c0_), ah0, v0);
        cp_async16(sb + 2 * (so + H_OAH + r1_ * 40 + c0_), ah1, v1);
        cp_async16(sb + 2 * (so + H_OAL + r0_ * 40 + c0_), al0, v0);
        cp_async16(sb + 2 * (so + H_OAL + r1_ * 40 + c0_), al1, v1);
        size_t gb0 = (size_t)(n0 + r0_) * K + kc * 32 + c0_;
        size_t gb1 = (size_t)(n0 + r1_) * K + kc * 32 + c0_;
        cp_async16(sb + 2 * (so + H_OBH + r0_ * 40 + c0_), Bh + gb0, true);
        cp_async16(sb + 2 * (so + H_OBH + r1_ * 40 + c0_), Bh + gb1, true);
        cp_async16(sb + 2 * (so + H_OBL + r0_ * 40 + c0_), Bl + gb0, true);
        cp_async16(sb + 2 * (so + H_OBL + r1_ * 40 + c0_), Bl + gb1, true);
    };

    int nc = K >> 5;
    load_stage(0, 0);
    CP_COMMIT();

    for (int kc = 0; kc < nc; kc++) {
        if (kc + 1 < nc) {
            load_stage(kc + 1, (kc + 1) & 1);
            CP_COMMIT();
            CP_WAIT(1);
        } else {
            CP_WAIT(0);
        }
        __syncthreads();

        uint32_t so = (uint32_t)(kc & 1) * H_ST;
#pragma unroll
        for (int ks = 0; ks < 2; ks++) {
            int kk = ks * 16;
            uint32_t ah[2][4], al[2][4], bh[4][4], bl[4][4];
#pragma unroll
            for (int mt = 0; mt < 2; mt++) {
                uint32_t ro = (mw * 32 + mt * 16 + a_row) * 40 + kk + a_col;
                LDSM_X4(ah[mt], sb + 2 * (so + H_OAH + ro));
                LDSM_X4(al[mt], sb + 2 * (so + H_OAL + ro));
            }
#pragma unroll
            for (int np = 0; np < 4; np++) {
                uint32_t ro = (nw * 64 + np * 16 + b_row) * 40 + kk + b_col;
                LDSM_X4(bh[np], sb + 2 * (so + H_OBH + ro));
                LDSM_X4(bl[np], sb + 2 * (so + H_OBL + ro));
            }
#pragma unroll
            for (int mt = 0; mt < 2; mt++)
#pragma unroll
                for (int nt = 0; nt < 8; nt++) {
                    int hp = nt >> 1, pp = (nt & 1) * 2;
                    MMA16816(acc[mt][nt], ah[mt], bh[hp][pp], bh[hp][pp+1]);
                    MMA16816(acc[mt][nt], ah[mt], bl[hp][pp], bl[hp][pp+1]);
                    MMA16816(acc[mt][nt], al[mt], bh[hp][pp], bh[hp][pp+1]);
                }
        }
        __syncthreads();
    }

    int g = lane >> 2, t = lane & 3;
#pragma unroll
    for (int mt = 0; mt < 2; mt++)
#pragma unroll
        for (int nt = 0; nt < 8; nt++) {
            int row = m0 + mw * 32 + mt * 16 + g;
            int col = n0 + nw * 64 + nt * 8 + t * 2;
            if (row < M)
                *(float2*)&C[(size_t)row * N + col] =
                    make_float2(acc[mt][nt][0], acc[mt][nt][1]);
            if (row + 8 < M)
                *(float2*)&C[(size_t)(row + 8) * N + col] =
                    make_float2(acc[mt][nt][2], acc[mt][nt][3]);
        }
}

// ==== out_proj GEMM with fused residual-add + rmsnorm epilogue ================
// BM=128, BN=192 (full DM), K=384. grid (1, 101). Writes g_resid (+= residual)
// and, when nwp != nullptr, g_ah/g_al = split(rmsnorm(r) * nwp).
#define O_ST   25600
#define O_OAH  0
#define O_OAL  5120
#define O_OBH  10240
#define O_OBL  17920
#define GEMMOUT_SMEM_BYTES (2 * O_ST * 2)   // 102400

__global__ void __launch_bounds__(256, 1)
gemm_mma_out(const __nv_bfloat16* __restrict__ Ah, const __nv_bfloat16* __restrict__ Al,
             const __nv_bfloat16* __restrict__ Bh, const __nv_bfloat16* __restrict__ Bl,
             const float* __restrict__ nwp, int M) {
    extern __shared__ __nv_bfloat16 smbuf[];
    const uint32_t sb = smem_to_u32(smbuf);
    const int K = DI;
    int tid = threadIdx.x, lane = tid & 31, wid = tid >> 5;
    int mw = wid & 3, nw = wid >> 2;       // 4 M-warps x 2 N-warps (warp tile 32x96)
    int m0 = blockIdx.y * 128;

    float acc[2][12][4] = {};
    int sub = lane >> 3, rin = lane & 7;
    int a_row = rin + (sub & 1) * 8;
    int a_col = (sub >> 1) * 8;
    int b_row = rin + (sub >> 1) * 8;
    int b_col = (sub & 1) * 8;

    int ar0 = tid >> 2,  ac0 = (tid & 3) * 8;
    int ar1 = ar0 + 64;
    int br0 = tid >> 2, br1 = br0 + 64, br2 = br0 + 128;

    auto load_stage = [&](int kc, int s) {
        uint32_t so = (uint32_t)s * O_ST;
        bool v0 = (m0 + ar0 < M);
        bool v1 = (m0 + ar1 < M);
        const __nv_bfloat16* ah0 = Ah + (v0 ? ((size_t)(m0 + ar0) * K + kc * 32 + ac0) : 0);
        const __nv_bfloat16* ah1 = Ah + (v1 ? ((size_t)(m0 + ar1) * K + kc * 32 + ac0) : 0);
        const __nv_bfloat16* al0 = Al + (v0 ? ((size_t)(m0 + ar0) * K + kc * 32 + ac0) : 0);
        const __nv_bfloat16* al1 = Al + (v1 ? ((size_t)(m0 + ar1) * K + kc * 32 + ac0) : 0);
        cp_async16(sb + 2 * (so + O_OAH + ar0 * 40 + ac0), ah0, v0);
        cp_async16(sb + 2 * (so + O_OAH + ar1 * 40 + ac0), ah1, v1);
        cp_async16(sb + 2 * (so + O_OAL + ar0 * 40 + ac0), al0, v0);
        cp_async16(sb + 2 * (so + O_OAL + ar1 * 40 + ac0), al1, v1);
        size_t g0 = (size_t)br0 * K + kc * 32 + ac0;
        size_t g1 = (size_t)br1 * K + kc * 32 + ac0;
        size_t g2 = (size_t)br2 * K + kc * 32 + ac0;
        cp_async16(sb + 2 * (so + O_OBH + br0 * 40 + ac0), Bh + g0, true);
        cp_async16(sb + 2 * (so + O_OBH + br1 * 40 + ac0), Bh + g1, true);
        cp_async16(sb + 2 * (so + O_OBH + br2 * 40 + ac0), Bh + g2, true);
        cp_async16(sb + 2 * (so + O_OBL + br0 * 40 + ac0), Bl + g0, true);
        cp_async16(sb + 2 * (so + O_OBL + br1 * 40 + ac0), Bl + g1, true);
        cp_async16(sb + 2 * (so + O_OBL + br2 * 40 + ac0), Bl + g2, true);
    };

    int nc = K >> 5;    // 12
    load_stage(0, 0);
    CP_COMMIT();

    for (int kc = 0; kc < nc; kc++) {
        if (kc + 1 < nc) {
            load_stage(kc + 1, (kc + 1) & 1);
            CP_COMMIT();
            CP_WAIT(1);
        } else {
            CP_WAIT(0);
        }
        __syncthreads();

        uint32_t so = (uint32_t)(kc & 1) * O_ST;
#pragma unroll
        for (int ks = 0; ks < 2; ks++) {
            int kk = ks * 16;
            uint32_t ahf[2][4], alf[2][4];
#pragma unroll
            for (int mt = 0; mt < 2; mt++) {
                uint32_t ro = (mw * 32 + mt * 16 + a_row) * 40 + kk + a_col;
                LDSM_X4(ahf[mt], sb + 2 * (so + O_OAH + ro));
                LDSM_X4(alf[mt], sb + 2 * (so + O_OAL + ro));
            }
#pragma unroll
            for (int np = 0; np < 6; np++) {
                uint32_t bhf[4], blf[4];
                uint32_t ro = (nw * 96 + np * 16 + b_row) * 40 + kk + b_col;
                LDSM_X4(bhf, sb + 2 * (so + O_OBH + ro));
                LDSM_X4(blf, sb + 2 * (so + O_OBL + ro));
#pragma unroll
                for (int mt = 0; mt < 2; mt++)
#pragma unroll
                    for (int hf = 0; hf < 2; hf++) {
                        int pp = hf * 2;
                        MMA16816(acc[mt][np*2+hf], ahf[mt], bhf[pp], bhf[pp+1]);
                        MMA16816(acc[mt][np*2+hf], ahf[mt], blf[pp], blf[pp+1]);
                        MMA16816(acc[mt][np*2+hf], alf[mt], bhf[pp], bhf[pp+1]);
                    }
            }
        }
        __syncthreads();
    }

    // ---------------- fused epilogue: r = acc + resid; rmsnorm ----------------
    __syncthreads();
    float* sr = (float*)smbuf;                 // 128 rows x stride 194 floats
    float* srow = sr + 128 * 194;              // [128][2] row partial sums
    int g = lane >> 2, t = lane & 3;
    float ssl[2][2] = {};
#pragma unroll
    for (int mt = 0; mt < 2; mt++)
#pragma unroll
        for (int nt = 0; nt < 12; nt++) {
            int col = nw * 96 + nt * 8 + t * 2;
#pragma unroll
            for (int hr = 0; hr < 2; hr++) {
                int lrow = mw * 32 + mt * 16 + g + hr * 8;
                int row = m0 + lrow;
                float2 rv = make_float2(0.f, 0.f);
                if (row < M) {
                    float2 res = *(const float2*)&g_resid[(size_t)row * DM + col];
                    rv.x = acc[mt][nt][hr*2]     + res.x;
                    rv.y = acc[mt][nt][hr*2 + 1] + res.y;
                }
                sr[lrow * 194 + col]     = rv.x;
                sr[lrow * 194 + col + 1] = rv.y;
                ssl[mt][hr] += rv.x * rv.x + rv.y * rv.y;
            }
        }
    // reduce over the 4 t-lanes
#pragma unroll
    for (int mt = 0; mt < 2; mt++)
#pragma unroll
        for (int hr = 0; hr < 2; hr++) {
            float s = ssl[mt][hr];
            s += __shfl_xor_sync(0xffffffffu, s, 1);
            s += __shfl_xor_sync(0xffffffffu, s, 2);
            ssl[mt][hr] = s;
        }
    if (t == 0) {
#pragma unroll
        for (int mt = 0; mt < 2; mt++)
#pragma unroll
            for (int hr = 0; hr < 2; hr++) {
                int lrow = mw * 32 + mt * 16 + g + hr * 8;
                srow[lrow * 2 + nw] = ssl[mt][hr];
            }
    }
    __syncthreads();

    bool hasNorm = (nwp != nullptr);
    for (int idx = tid; idx < 128 * DM; idx += 256) {
        int lrow = idx / DM, col = idx - lrow * DM;
        int row = m0 + lrow;
        if (row >= M) break;
        float r = sr[lrow * 194 + col];
        g_resid[(size_t)row * DM + col] = r;
        if (hasNorm) {
            float ss = srow[lrow * 2] + srow[lrow * 2 + 1];
            float s = rsqrtf(ss * (1.0f / 192.0f) + 1e-5f);
            float x = r * s * nwp[col];
            __nv_bfloat16 h, l;
            split_bf16(x, h, l);
            g_ah[(size_t)row * DM + col] = h;
            g_al[(size_t)row * DM + col] = l;
        }
    }
}

// ------------- merged weight conversion (all three weight sets) ---------------
__global__ void cvt_all_kernel(const float* __restrict__ in_w,
                               const float* __restrict__ xp,
                               const float* __restrict__ ow) {
    const int n1 = 4*768*DM;
    const int n2 = 4*64*DI;
    const int n3 = 4*DM*DI;
    int i = blockIdx.x * blockDim.x + threadIdx.x;
    if (i < n1) {
        __nv_bfloat16 h, l;
        split_bf16(in_w[i], h, l);
        g_wih[i] = h; g_wil[i] = l;
    } else if (i < n1 + n2) {
        int j = i - n1;
        int k = j % DI;
        int r = (j / DI) % 64;
        int lyr = j / (64 * DI);
        float v = (r < XD) ? xp[((size_t)lyr * XD + r) * DI + k] : 0.f;
        __nv_bfloat16 h, l;
        split_bf16(v, h, l);
        g_wxh[j] = h; g_wxl[j] = l;
    } else if (i < n1 + n2 + n3) {
        int j = i - n1 - n2;
        __nv_bfloat16 h, l;
        split_bf16(ow[j], h, l);
        g_woh[j] = h; g_wol[j] = l;
    }
}

// ------------- embed + first rmsnorm fused: one block per token --------------
__global__ void embed_norm_kernel(const float* __restrict__ imgs,
                                  const float* __restrict__ pw,
                                  const float* __restrict__ pb,
                                  const float* __restrict__ pos,
                                  const float* __restrict__ clstok,
                                  const float* __restrict__ nw) {
    __shared__ float red[6];
    int t = blockIdx.x;
    int m = threadIdx.x;
    int b = t / LSEQ;
    int l = t - b * LSEQ;
    float v;
    if (l < 400) {
        const float* ip = imgs + b * 1600 + l * 4;
        v = pb[m]
          + ip[0] * pw[0*DM + m] + ip[1] * pw[1*DM + m]
          + ip[2] * pw[2*DM + m] + ip[3] * pw[3*DM + m]
          + pos[l*DM + m];
    } else {
        v = clstok[m] + pos[400*DM + m];
    }
    g_resid[t*DM + m] = v;
    float ss = v * v;
#pragma unroll
    for (int o = 16; o; o >>= 1) ss += __shfl_xor_sync(0xffffffffu, ss, o);
    if ((m & 31) == 0) red[m >> 5] = ss;
    __syncthreads();
    float tot = red[0] + red[1] + red[2] + red[3] + red[4] + red[5];
    float s = rsqrtf(tot * (1.0f/192.0f) + 1e-5f);
    float x = v * s * nw[m];
    __nv_bfloat16 h, lo;
    split_bf16(x, h, lo);
    g_ah[t*DM + m] = h;
    g_al[t*DM + m] = lo;
}

// ------ depthwise causal conv (k=4) + SiLU: 4 tokens x 4 channels per thread --
#define NTG 101
__global__ void conv_silu_kernel(const float* __restrict__ cw,
                                 const float* __restrict__ cb) {
    int idx = blockIdx.x * blockDim.x + threadIdx.x;
    if (idx >= BATCH * NTG * (DI/4)) return;
    int d4  = idx % (DI/4);
    int rem = idx / (DI/4);
    int gr  = rem % NTG;
    int b   = rem / NTG;
    int l0  = gr * 4;
    int d   = d4 * 4;
    float4 w0 = *(const float4*)&cw[(d+0)*4];
    float4 w1 = *(const float4*)&cw[(d+1)*4];
    float4 w2 = *(const float4*)&cw[(d+2)*4];
    float4 w3 = *(const float4*)&cw[(d+3)*4];
    float4 bias = *(const float4*)&cb[d];

    float4 xb[7];
#pragma unroll
    for (int j = 0; j < 7; j++) {
        int l = l0 + j - 3;
        if (l >= 0 && l < LSEQ)
            xb[j] = *(const float4*)&g_xz[((size_t)b*LSEQ + l)*768 + d];
        else
            xb[j] = make_float4(0.f, 0.f, 0.f, 0.f);
    }
#pragma unroll
    for (int i = 0; i < 4; i++) {
        int l = l0 + i;
        if (l < LSEQ) {
            float4 acc = bias;
            acc.x += w0.x*xb[i].x + w0.y*xb[i+1].x + w0.z*xb[i+2].x + w0.w*xb[i+3].x;
            acc.y += w1.x*xb[i].y + w1.y*xb[i+1].y + w1.z*xb[i+2].y + w1.w*xb[i+3].y;
            acc.z += w2.x*xb[i].z + w2.y*xb[i+1].z + w2.z*xb[i+2].z + w2.w*xb[i+3].z;
            acc.w += w3.x*xb[i].w + w3.y*xb[i+1].w + w3.z*xb[i+2].w + w3.w*xb[i+3].w;
            float4 o;
            o.x = acc.x / (1.f + __expf(-acc.x));
            o.y = acc.y / (1.f + __expf(-acc.y));
            o.z = acc.z / (1.f + __expf(-acc.z));
            o.w = acc.w / (1.f + __expf(-acc.w));
            size_t t = (size_t)b*LSEQ + l;
            *(float4*)&g_uconv[t*DI + d] = o;
            __nv_bfloat16 h0,q0,h1,q1,h2,q2,h3,q3;
            split_bf16(o.x, h0, q0); split_bf16(o.y, h1, q1);
            split_bf16(o.z, h2, q2); split_bf16(o.w, h3, q3);
            __nv_bfloat162* ph = (__nv_bfloat162*)&g_uh[t*DI + d];
            __nv_bfloat162* pl = (__nv_bfloat162*)&g_ul[t*DI + d];
            ph[0] = __halves2bfloat162(h0, h1); ph[1] = __halves2bfloat162(h2, h3);
            pl[0] = __halves2bfloat162(q0, q1); pl[1] = __halves2bfloat162(q2, q3);
        }
    }
}

// -------------- dt projection + softplus (smem-tiled, 32 tokens/block) -------
__global__ void dt_kernel(const float* __restrict__ dtw,
                          const float* __restrict__ dtb) {
    __shared__ float dtw_s[DTR * DI];
    __shared__ float dtb_s[DI];
    __shared__ float xr_s[32 * DTR];
    int tid = threadIdx.x;              // 384
    int t0 = blockIdx.x * 32;
#pragma unroll
    for (int k = 0; k < DTR; k++) {
        int i = tid + k * DI;
        int d_ = i / DTR, r_ = i % DTR;
        dtw_s[r_ * DI + d_] = dtw[i];
    }
    dtb_s[tid] = dtb[tid];
    {
        int tok = tid / DTR, r = tid % DTR;
        if (tok < 32) xr_s[tok * DTR + r] = g_xdbl[(size_t)(t0 + tok) * XD + r];
    }
    __syncthreads();
    int d = tid;
    float w[DTR];
#pragma unroll
    for (int r = 0; r < DTR; r++) w[r] = dtw_s[r * DI + d];
    float bsv = dtb_s[d];
    for (int tok = 0; tok < 32; tok++) {
        float s = bsv;
#pragma unroll
        for (int r = 0; r < DTR; r++) s += xr_s[tok * DTR + r] * w[r];
        float sp = fmaxf(s, 0.f) + log1pf(__expf(-fabsf(s)));
        g_dt[(size_t)(t0 + tok) * DI + d] = sp;
    }
}

// ======================= chunked parallel selective scan =======================
__global__ void scan_p1(const float* __restrict__ A_log) {
    int b = blockIdx.x;
    int d = blockIdx.y * 128 + threadIdx.x;
    int c = blockIdx.z;
    int warp = threadIdx.x >> 5, lane = threadIdx.x & 31;
    __shared__ float bcs[4][3][16];
    float An[DS], h[DS];
#pragma unroll
    for (int n = 0; n < DS; n++) {
        An[n] = -expf(A_log[d*DS + n]);
        h[n] = 0.f;
    }
    bool structured = true;
#pragma unroll
    for (int n = 1; n < DS; n++)
        structured = structured &&
            (fabsf(An[n] - (float)(n+1)*An[0]) <= 1e-4f*fabsf(An[n]) + 1e-6f);

    int l0 = c * CL;
    int steps = CL;
    const float* xb  = g_xdbl  + ((size_t)b*LSEQ + l0)*XD + 12;
    const float* dtp = g_dt    + ((size_t)b*LSEQ + l0)*DI + d;
    const float* up  = g_uconv + ((size_t)b*LSEQ + l0)*DI + d;

    float bcr1 = 0.f, dt0, u0, dt1 = 0.f, u1 = 0.f;
    if (lane < 16) bcs[warp][0][lane] = xb[lane];
    dt0 = dtp[0]; u0 = up[0];
    if (steps > 1) {
        if (lane < 16) bcr1 = xb[XD + lane];
        dt1 = dtp[DI]; u1 = up[DI];
    }
    __syncwarp();

    float S = 0.f;
    for (int i = 0; i < steps; i++) {
        if (i + 1 < steps && lane < 16) bcs[warp][(i+1)%3][lane] = bcr1;
        float bcr2 = 0.f, dt2 = 0.f, u2 = 0.f;
        if (i + 2 < steps) {
            if (lane < 16) bcr2 = xb[(size_t)(i+2)*XD + lane];
            dt2 = dtp[(size_t)(i+2)*DI];
            u2  = up [(size_t)(i+2)*DI];
        }
        __syncwarp();
        const float* Bc = bcs[warp][i % 3];
        float dtv = dt0, uv = u0;
        float dtu = dtv * uv;
        S += dtv;
        if (structured) {
            float E = __expf(dtv * An[0]);
            float P = E;
#pragma unroll
            for (int n = 0; n < DS; n++) {
                h[n] = P * h[n] + dtu * Bc[n];
                P *= E;
            }
        } else {
#pragma unroll
            for (int n = 0; n < DS; n++) {
                float dA = __expf(dtv * An[n]);
                h[n] = dA * h[n] + dtu * Bc[n];
            }
        }
        dt0 = dt1; u0 = u1;
        dt1 = dt2; u1 = u2;
        bcr1 = bcr2;
    }

    size_t base = (((size_t)b*NCHUNK + c)*DI + d)*DS;
    float P[DS];
    if (structured) {
        float E = __expf(S * An[0]);
        float pp = E;
#pragma unroll
        for (int n = 0; n < DS; n++) { P[n] = pp; pp *= E; }
    } else {
#pragma unroll
        for (int n = 0; n < DS; n++) P[n] = __expf(S * An[n]);
    }
#pragma unroll
    for (int q = 0; q < 4; q++) {
        *(float4*)&g_scanF[base + q*4] = make_float4(h[q*4], h[q*4+1], h[q*4+2], h[q*4+3]);
        *(float4*)&g_scanP[base + q*4] = make_float4(P[q*4], P[q*4+1], P[q*4+2], P[q*4+3]);
    }
}

__global__ void scan_mid() {
    int b = blockIdx.x;
    int d = blockIdx.y * 128 + threadIdx.x;
    float H[DS];
#pragma unroll
    for (int n = 0; n < DS; n++) H[n] = 0.f;
    for (int c = 0; c < NCHUNK - 1; c++) {
        size_t base = (((size_t)b*NCHUNK + c)*DI + d)*DS;
#pragma unroll
        for (int q = 0; q < 4; q++) {
            float4 F = *(const float4*)&g_scanF[base + q*4];
            float4 P = *(const float4*)&g_scanP[base + q*4];
            H[q*4+0] = F.x + P.x * H[q*4+0];
            H[q*4+1] = F.y + P.y * H[q*4+1];
            H[q*4+2] = F.z + P.z * H[q*4+2];
            H[q*4+3] = F.w + P.w * H[q*4+3];
        }
        size_t ibase = (((size_t)b*NCHUNK + c + 1)*DI + d)*DS;
#pragma unroll
        for (int q = 0; q < 4; q++)
            *(float4*)&g_scanI[ibase + q*4] =
                make_float4(H[q*4], H[q*4+1], H[q*4+2], H[q*4+3]);
    }
}

__global__ void scan_p3(const float* __restrict__ A_log,
                        const float* __restrict__ Dv) {
    int b = blockIdx.x;
    int d = blockIdx.y * 128 + threadIdx.x;
    int c = blockIdx.z;
    int warp = threadIdx.x >> 5, lane = threadIdx.x & 31;
    __shared__ float bcs[4][3][32];
    float An[DS], h[DS];
#pragma unroll
    for (int n = 0; n < DS; n++) An[n] = -expf(A_log[d*DS + n]);
    bool structured = true;
#pragma unroll
    for (int n = 1; n < DS; n++)
        structured = structured &&
            (fabsf(An[n] - (float)(n+1)*An[0]) <= 1e-4f*fabsf(An[n]) + 1e-6f);

    if (c == 0) {
#pragma unroll
        for (int n = 0; n < DS; n++) h[n] = 0.f;
    } else {
        size_t ibase = (((size_t)b*NCHUNK + c)*DI + d)*DS;
#pragma unroll
        for (int q = 0; q < 4; q++) {
            float4 v = *(const float4*)&g_scanI[ibase + q*4];
            h[q*4+0] = v.x; h[q*4+1] = v.y; h[q*4+2] = v.z; h[q*4+3] = v.w;
        }
    }

    int l0 = c * CL;
    int le = min(LSEQ, l0 + CL);
    int steps = le - l0;
    float Dd = Dv[d];
    const float* xb  = g_xdbl  + ((size_t)b*LSEQ + l0)*XD + 12;
    const float* dtp = g_dt    + ((size_t)b*LSEQ + l0)*DI + d;
    const float* up  = g_uconv + ((size_t)b*LSEQ + l0)*DI + d;
    const float* zp  = g_xz    + ((size_t)b*LSEQ + l0)*768 + DI + d;
    __nv_bfloat16* yhp = g_yh + ((size_t)b*LSEQ + l0)*DI + d;
    __nv_bfloat16* ylp = g_yl + ((size_t)b*LSEQ + l0)*DI + d;

    float bcr1 = 0.f, dt0, u0, z0, dt1 = 0.f, u1 = 0.f, z1 = 0.f;
    bcs[warp][0][lane] = xb[lane];
    dt0 = dtp[0]; u0 = up[0]; z0 = zp[0];
    if (steps > 1) {
        bcr1 = xb[XD + lane];
        dt1 = dtp[DI]; u1 = up[DI]; z1 = zp[768];
    }
    __syncwarp();

    for (int i = 0; i < steps; i++) {
        if (i + 1 < steps) bcs[warp][(i+1)%3][lane] = bcr1;
        float bcr2 = 0.f, dt2 = 0.f, u2 = 0.f, z2 = 0.f;
        if (i + 2 < steps) {
            bcr2 = xb[(size_t)(i+2)*XD + lane];
            dt2  = dtp[(size_t)(i+2)*DI];
            u2   = up [(size_t)(i+2)*DI];
            z2   = zp [(size_t)(i+2)*768];
        }
        __syncwarp();
        const float* BCc = bcs[warp][i % 3];
        float dtv = dt0, uv = u0, zv = z0;
        float dtu = dtv * uv;
        float y = 0.f;
        if (structured) {
            float E = __expf(dtv * An[0]);
            float P = E;
#pragma unroll
            for (int n = 0; n < DS; n++) {
                h[n] = P * h[n] + dtu * BCc[n];
                y += h[n] * BCc[16 + n];
                P *= E;
            }
        } else {
#pragma unroll
            for (int n = 0; n < DS; n++) {
                float dA = __expf(dtv * An[n]);
                h[n] = dA * h[n] + dtu * BCc[n];
                y += h[n] * BCc[16 + n];
            }
        }
        y += uv * Dd;
        float sz = zv / (1.f + __expf(-zv));
        float yo = y * sz;
        __nv_bfloat16 hh, ll;
        split_bf16(yo, hh, ll);
        yhp[(size_t)i * DI] = hh;
        ylp[(size_t)i * DI] = ll;
        dt0 = dt1; u0 = u1; z0 = z1;
        dt1 = dt2; u1 = u2; z1 = z2;
        bcr1 = bcr2;
    }
}

// ------ final norm on cls tokens only (resid already holds hidden+resid) -----
__global__ void final_norm_kernel(const float* __restrict__ normf) {
    int warp = threadIdx.x >> 5, lane = threadIdx.x & 31;
    int b = blockIdx.x * 8 + warp;
    if (b >= BATCH) return;
    int t = b * LSEQ + 400;
    float v[6];
    float ss = 0.f;
#pragma unroll
    for (int i = 0; i < 6; i++) {
        int m = lane + i*32;
        float r = g_resid[t*DM + m];
        v[i] = r;
        ss += r * r;
    }
#pragma unroll
    for (int o = 16; o; o >>= 1) ss += __shfl_xor_sync(0xffffffffu, ss, o);
    float s = rsqrtf(ss * (1.0f/192.0f) + 1e-5f);
#pragma unroll
    for (int i = 0; i < 6; i++) {
        int m = lane + i*32;
        g_cls[b*DM + m] = v[i] * s * normf[m];
    }
}

// -------------- FFMA2 GEMM (head only): C = A[M,K] * B[N,K]^T + bias ---------
template<int BN, int TN>
__global__ void __launch_bounds__(256, 2)
gemm_ffma2(const float* __restrict__ A,
           const float* __restrict__ Bw,
           const float* __restrict__ bias,
           float* __restrict__ C,
           int M, int N, int K) {
    constexpr int BM = 128, BK = 16;
    constexpr int NTX = BN / TN;
    __shared__ float As[BK][BM + 4];
    __shared__ float Bs[BK][BN + 4];
    int tid = threadIdx.x;
    int tx = tid % NTX, ty = tid / NTX;
    int row0 = blockIdx.y * BM, col0 = blockIdx.x * BN;
    unsigned long long acc[4][TN];
#pragma unroll
    for (int i = 0; i < 4; i++)
#pragma unroll
        for (int j = 0; j < TN; j++) acc[i][j] = 0ull;
    int lr  = tid >> 2;
    int lc4 = (tid & 3) * 4;
    for (int k0 = 0; k0 < K; k0 += BK) {
#pragma unroll
        for (int h = 0; h < 2; h++) {
            int rr = lr + h * 64;
            float4 v = make_float4(0.f, 0.f, 0.f, 0.f);
            if (row0 + rr < M)
                v = *(const float4*)&A[(size_t)(row0 + rr) * K + k0 + lc4];
            As[lc4+0][rr] = v.x; As[lc4+1][rr] = v.y;
            As[lc4+2][rr] = v.z; As[lc4+3][rr] = v.w;
        }
        constexpr int NB = (BN * BK) / (256 * 4);
#pragma unroll
        for (int h = 0; h < NB; h++) {
            int nn = lr + h * 64;
            float4 v = make_float4(0.f, 0.f, 0.f, 0.f);
            if (col0 + nn < N)
                v = *(const float4*)&Bw[(size_t)(col0 + nn) * K + k0 + lc4];
            Bs[lc4+0][nn] = v.x; Bs[lc4+1][nn] = v.y;
            Bs[lc4+2][nn] = v.z; Bs[lc4+3][nn] = v.w;
        }
        __syncthreads();
#pragma unroll
        for (int k = 0; k < BK; k++) {
            ulonglong2 a01 = *(const ulonglong2*)&As[k][ty * 8];
            ulonglong2 a23 = *(const ulonglong2*)&As[k][ty * 8 + 4];
            unsigned long long ap[4] = { a01.x, a01.y, a23.x, a23.y };
            unsigned long long bp[TN];
            float4 b0 = *(const float4*)&Bs[k][tx * TN];
            asm("mov.b64 %0, {%1, %1};" : "=l"(bp[0]) : "f"(b0.x));
            asm("mov.b64 %0, {%1, %1};" : "=l"(bp[1]) : "f"(b0.y));
            asm("mov.b64 %0, {%1, %1};" : "=l"(bp[2]) : "f"(b0.z));
            asm("mov.b64 %0, {%1, %1};" : "=l"(bp[3]) : "f"(b0.w));
            if (TN == 8) {
                float4 b1 = *(const float4*)&Bs[k][tx * TN + 4];
                asm("mov.b64 %0, {%1, %1};" : "=l"(bp[4]) : "f"(b1.x));
                asm("mov.b64 %0, {%1, %1};" : "=l"(bp[5]) : "f"(b1.y));
                asm("mov.b64 %0, {%1, %1};" : "=l"(bp[6]) : "f"(b1.z));
                asm("mov.b64 %0, {%1, %1};" : "=l"(bp[7]) : "f"(b1.w));
            }
#pragma unroll
            for (int i = 0; i < 4; i++)
#pragma unroll
                for (int j = 0; j < TN; j++)
                    asm("fma.rn.f32x2 %0, %1, %2, %0;"
                        : "+l"(acc[i][j]) : "l"(ap[i]), "l"(bp[j]));
        }
        __syncthreads();
    }
#pragma unroll
    for (int i = 0; i < 4; i++) {
        int r0 = row0 + ty * 8 + 2 * i;
#pragma unroll
        for (int j = 0; j < TN; j++) {
            int c = col0 + tx * TN + j;
            if (c < N) {
                float lo, hi;
                asm("mov.b64 {%0, %1}, %2;" : "=f"(lo), "=f"(hi) : "l"(acc[i][j]));
                float bv = bias ? bias[c] : 0.f;
                if (r0 < M)     C[(size_t)r0 * N + c]       = lo + bv;
                if (r0 + 1 < M) C[(size_t)(r0 + 1) * N + c] = hi + bv;
            }
        }
    }
}

// ==============================================================================
extern "C" void kernel_launch(void* const* d_in, const int* in_sizes, int n_in,
                              void* d_out, int out_size) {
    const float* imgs      = (const float*)d_in[0];
    const float* patch_w   = (const float*)d_in[1];
    const float* patch_b   = (const float*)d_in[2];
    const float* pos_embed = (const float*)d_in[3];
    const float* cls_token = (const float*)d_in[4];
    const float* norm_w    = (const float*)d_in[5];
    const float* in_proj_w = (const float*)d_in[6];
    const float* conv_w    = (const float*)d_in[7];
    const float* conv_b    = (const float*)d_in[8];
    const float* xproj_w   = (const float*)d_in[9];
    const float* dt_w      = (const float*)d_in[10];
    const float* dt_b      = (const float*)d_in[11];
    const float* A_log     = (const float*)d_in[12];
    const float* D_param   = (const float*)d_in[13];
    const float* out_w     = (const float*)d_in[14];
    const float* normf_w   = (const float*)d_in[15];
    const float* head_w    = (const float*)d_in[16];
    const float* head_b    = (const float*)d_in[17];
    float* out = (float*)d_out;

    float *p_xz, *p_xdbl, *p_cls;
    cudaGetSymbolAddress((void**)&p_xz,     g_xz);
    cudaGetSymbolAddress((void**)&p_xdbl,   g_xdbl);
    cudaGetSymbolAddress((void**)&p_cls,    g_cls);
    __nv_bfloat16 *p_ah, *p_al, *p_uh, *p_ul, *p_yh, *p_yl;
    __nv_bfloat16 *p_wih, *p_wil, *p_wxh, *p_wxl, *p_woh, *p_wol;
    cudaGetSymbolAddress((void**)&p_ah, g_ah);   cudaGetSymbolAddress((void**)&p_al, g_al);
    cudaGetSymbolAddress((void**)&p_uh, g_uh);   cudaGetSymbolAddress((void**)&p_ul, g_ul);
    cudaGetSymbolAddress((void**)&p_yh, g_yh);   cudaGetSymbolAddress((void**)&p_yl, g_yl);
    cudaGetSymbolAddress((void**)&p_wih, g_wih); cudaGetSymbolAddress((void**)&p_wil, g_wil);
    cudaGetSymbolAddress((void**)&p_wxh, g_wxh); cudaGetSymbolAddress((void**)&p_wxl, g_wxl);
    cudaGetSymbolAddress((void**)&p_woh, g_woh); cudaGetSymbolAddress((void**)&p_wol, g_wol);

    cudaFuncSetAttribute(gemm_mma, cudaFuncAttributeMaxDynamicSharedMemorySize,
                         GEMM_SMEM_BYTES);
    cudaFuncSetAttribute(gemm_mma128, cudaFuncAttributeMaxDynamicSharedMemorySize,
                         GEMM128_SMEM_BYTES);
    cudaFuncSetAttribute(gemm_mma_out, cudaFuncAttributeMaxDynamicSharedMemorySize,
                         GEMMOUT_SMEM_BYTES);

    const int CVT_N = 4*768*DM + 4*64*DI + 4*DM*DI;
    cvt_all_kernel<<<(CVT_N + 255)/256, 256>>>(in_proj_w, xproj_w, out_w);

    embed_norm_kernel<<<NTOK, DM>>>(imgs, patch_w, patch_b, pos_embed, cls_token,
                                    norm_w);

    const int MT = (NTOK + 127) / 128;   // 101

    for (int i = 0; i < 4; i++) {
        // in_proj: 128x128 tile (N=768 -> 6 column blocks)
        gemm_mma128<<<dim3(6, MT), 256, GEMM128_SMEM_BYTES>>>(
            p_ah, p_al, p_wih + (size_t)i*768*DM, p_wil + (size_t)i*768*DM,
            p_xz, NTOK, 768, DM);

        conv_silu_kernel<<<(BATCH*NTG*(DI/4) + 255)/256, 256>>>(
            conv_w + i*DI*4, conv_b + i*DI);

        gemm_mma<<<dim3(1, MT), 256, GEMM_SMEM_BYTES>>>(
            p_uh, p_ul, p_wxh + (size_t)i*64*DI, p_wxl + (size_t)i*64*DI,
            p_xdbl, NTOK, XD, DI);

        dt_kernel<<<NTOK/32, 384>>>(dt_w + i*DI*DTR, dt_b + i*DI);

        scan_p1<<<dim3(BATCH, 3, NCHUNK-1), 128>>>(A_log + (size_t)i*DI*DS);
        scan_mid<<<dim3(BATCH, 3), 128>>>();
        scan_p3<<<dim3(BATCH, 3, NCHUNK), 128>>>(A_log + (size_t)i*DI*DS, D_param + i*DI);

        // out_proj with fused residual add + rmsnorm (next layer's norm weight)
        gemm_mma_out<<<dim3(1, MT), 256, GEMMOUT_SMEM_BYTES>>>(
            p_yh, p_yl, p_woh + (size_t)i*DM*DI, p_wol + (size_t)i*DM*DI,
            (i < 3) ? (norm_w + (i+1)*DM) : nullptr, NTOK);
    }

    final_norm_kernel<<<(BATCH + 7)/8, 256>>>(normf_w);

    gemm_ffma2<128,8><<<dim3((NCLS + 127)/128, 1), 256>>>(
        p_cls, head_w, head_b, out, BATCH, NCLS, DM);
}

// round 16
// speedup vs baseline: 1.0503x; 1.0503x over previous
#include <cuda_runtime.h>
#include <cuda_bf16.h>
#include <math.h>
#include <stdint.h>

#define BATCH 32
#define LSEQ  401
#define NTOK  (BATCH*LSEQ)       // 12832
#define DM    192
#define DI    384
#define DS    16
#define DTR   12
#define XD    44                  // DT_RANK + 2*D_STATE
#define NCLS  1000
#define NCHUNK 8
#define CL    51                  // ceil(401/8)

__device__ __forceinline__ uint32_t smem_to_u32(const void* p) {
    uint32_t a;
    asm("{ .reg .u64 t; cvta.to.shared.u64 t, %1; cvt.u32.u64 %0, t; }"
        : "=r"(a) : "l"(p));
    return a;
}

__device__ __forceinline__ void split_bf16(float x, __nv_bfloat16& h, __nv_bfloat16& l) {
    h = __float2bfloat16(x);
    l = __float2bfloat16(x - __bfloat162float(h));
}

__device__ __forceinline__ void cp_async16(uint32_t dst, const void* src, bool pred) {
    int sz = pred ? 16 : 0;
    asm volatile("cp.async.cg.shared.global [%0], [%1], 16, %2;"
                 :: "r"(dst), "l"(src), "r"(sz));
}
#define CP_COMMIT() asm volatile("cp.async.commit_group;" ::: "memory")
#define CP_WAIT(n)  asm volatile("cp.async.wait_group %0;" :: "n"(n) : "memory")

// ---------------- scratch (device globals; no allocation allowed) -------------
__device__ float g_hidden[NTOK*DM];
__device__ float g_resid [NTOK*DM];
__device__ float g_xz    [NTOK*2*DI];
__device__ float g_uconv [NTOK*DI];
__device__ float g_xdbl  [NTOK*XD];
__device__ float g_dt    [NTOK*DI];
__device__ float g_cls   [BATCH*DM];
__device__ float g_scanF [BATCH*NCHUNK*DI*DS];
__device__ float g_scanP [BATCH*NCHUNK*DI*DS];
__device__ float g_scanI [BATCH*NCHUNK*DI*DS];

__device__ __nv_bfloat16 g_ah[NTOK*DM],  g_al[NTOK*DM];
__device__ __nv_bfloat16 g_uh[NTOK*DI],  g_ul[NTOK*DI];
__device__ __nv_bfloat16 g_yh[NTOK*DI],  g_yl[NTOK*DI];
__device__ __nv_bfloat16 g_wih[4*768*DM], g_wil[4*768*DM];
__device__ __nv_bfloat16 g_wxh[4*64*DI],  g_wxl[4*64*DI];
__device__ __nv_bfloat16 g_woh[4*DM*DI],  g_wol[4*DM*DI];

// ============ bf16 split-precision tensor-core GEMM (mma.sync/HMMA) ==========
#define LDSM_X4(f, addr) \
    asm volatile("ldmatrix.sync.aligned.m8n8.x4.shared.b16 {%0,%1,%2,%3}, [%4];" \
        : "=r"((f)[0]), "=r"((f)[1]), "=r"((f)[2]), "=r"((f)[3]) : "r"(addr))
#define MMA16816(c, a, b0, b1) \
    asm volatile("mma.sync.aligned.m16n8k16.row.col.f32.bf16.bf16.f32 " \
        "{%0,%1,%2,%3}, {%4,%5,%6,%7}, {%8,%9}, {%0,%1,%2,%3};" \
        : "+f"((c)[0]), "+f"((c)[1]), "+f"((c)[2]), "+f"((c)[3]) \
        : "r"((a)[0]), "r"((a)[1]), "r"((a)[2]), "r"((a)[3]), "r"(b0), "r"(b1))

// smem element offsets (bf16 units), row stride 40
#define G_ST   15360     // per-stage elements
#define G_OAH  0
#define G_OAL  5120
#define G_OBH  10240
#define G_OBL  12800
#define GEMM_SMEM_BYTES (2 * G_ST * 2)

__global__ void __launch_bounds__(256)
gemm_mma(const __nv_bfloat16* __restrict__ Ah, const __nv_bfloat16* __restrict__ Al,
         const __nv_bfloat16* __restrict__ Bh, const __nv_bfloat16* __restrict__ Bl,
         float* __restrict__ C, int M, int N, int K) {
    extern __shared__ __nv_bfloat16 smbuf[];
    const uint32_t sb = smem_to_u32(smbuf);
    int tid = threadIdx.x, lane = tid & 31, wid = tid >> 5;
    int mw = wid & 3, nw = wid >> 2;
    int m0 = blockIdx.y * 128, n0 = blockIdx.x * 64;

    float acc[2][4][4] = {};
    int sub = lane >> 3, rin = lane & 7;
    int a_row = rin + (sub & 1) * 8;
    int a_col = (sub >> 1) * 8;
    int b_row = rin + (sub >> 1) * 8;
    int b_col = (sub & 1) * 8;

    // per-thread load coordinates
    int ar0 = tid >> 2,  ac0 = (tid & 3) * 8;          // A chunk 0 (rows 0..63)
    int ar1 = ar0 + 64;                                 // A chunk 1 (rows 64..127)
    int br  = tid >> 2,  bc = (tid & 3) * 8;            // B (rows 0..63)

    auto load_stage = [&](int kc, int s) {
        uint32_t so = (uint32_t)s * G_ST;
        bool v0 = (m0 + ar0 < M);
        bool v1 = (m0 + ar1 < M);
        const __nv_bfloat16* ah0 = Ah + (v0 ? ((size_t)(m0 + ar0) * K + kc * 32 + ac0) : 0);
        const __nv_bfloat16* ah1 = Ah + (v1 ? ((size_t)(m0 + ar1) * K + kc * 32 + ac0) : 0);
        const __nv_bfloat16* al0 = Al + (v0 ? ((size_t)(m0 + ar0) * K + kc * 32 + ac0) : 0);
        const __nv_bfloat16* al1 = Al + (v1 ? ((size_t)(m0 + ar1) * K + kc * 32 + ac0) : 0);
        cp_async16(sb + 2 * (so + G_OAH + ar0 * 40 + ac0), ah0, v0);
        cp_async16(sb + 2 * (so + G_OAH + ar1 * 40 + ac0), ah1, v1);
        cp_async16(sb + 2 * (so + G_OAL + ar0 * 40 + ac0), al0, v0);
        cp_async16(sb + 2 * (so + G_OAL + ar1 * 40 + ac0), al1, v1);
        size_t gb = (size_t)(n0 + br) * K + kc * 32 + bc;
        cp_async16(sb + 2 * (so + G_OBH + br * 40 + bc), Bh + gb, true);
        cp_async16(sb + 2 * (so + G_OBL + br * 40 + bc), Bl + gb, true);
    };

    int nc = K >> 5;
    load_stage(0, 0);
    CP_COMMIT();

    for (int kc = 0; kc < nc; kc++) {
        if (kc + 1 < nc) {
            load_stage(kc + 1, (kc + 1) & 1);
            CP_COMMIT();
            CP_WAIT(1);
        } else {
            CP_WAIT(0);
        }
        __syncthreads();

        uint32_t so = (uint32_t)(kc & 1) * G_ST;
#pragma unroll
        for (int ks = 0; ks < 2; ks++) {
            int kk = ks * 16;
            uint32_t ah[2][4], al[2][4], bh[2][4], bl[2][4];
#pragma unroll
            for (int mt = 0; mt < 2; mt++) {
                uint32_t ro = (mw * 32 + mt * 16 + a_row) * 40 + kk + a_col;
                LDSM_X4(ah[mt], sb + 2 * (so + G_OAH + ro));
                LDSM_X4(al[mt], sb + 2 * (so + G_OAL + ro));
            }
#pragma unroll
            for (int np = 0; np < 2; np++) {
                uint32_t ro = (nw * 32 + np * 16 + b_row) * 40 + kk + b_col;
                LDSM_X4(bh[np], sb + 2 * (so + G_OBH + ro));
                LDSM_X4(bl[np], sb + 2 * (so + G_OBL + ro));
            }
#pragma unroll
            for (int mt = 0; mt < 2; mt++)
#pragma unroll
                for (int nt = 0; nt < 4; nt++) {
                    int hp = nt >> 1, pp = (nt & 1) * 2;
                    MMA16816(acc[mt][nt], ah[mt], bh[hp][pp], bh[hp][pp+1]);
                    MMA16816(acc[mt][nt], ah[mt], bl[hp][pp], bl[hp][pp+1]);
                    MMA16816(acc[mt][nt], al[mt], bh[hp][pp], bh[hp][pp+1]);
                }
        }
        __syncthreads();
    }

    int g = lane >> 2, t = lane & 3;
#pragma unroll
    for (int mt = 0; mt < 2; mt++)
#pragma unroll
        for (int nt = 0; nt < 4; nt++) {
            int row = m0 + mw * 32 + mt * 16 + g;
            int col = n0 + nw * 32 + nt * 8 + t * 2;
            if (col < N) {
                if (row < M)
                    *(float2*)&C[(size_t)row * N + col] =
                        make_float2(acc[mt][nt][0], acc[mt][nt][1]);
                if (row + 8 < M)
                    *(float2*)&C[(size_t)(row + 8) * N + col] =
                        make_float2(acc[mt][nt][2], acc[mt][nt][3]);
            }
        }
}

// ------------- merged weight conversion (all three weight sets) ---------------
__global__ void cvt_all_kernel(const float* __restrict__ in_w,
                               const float* __restrict__ xp,
                               const float* __restrict__ ow) {
    const int n1 = 4*768*DM;
    const int n2 = 4*64*DI;
    const int n3 = 4*DM*DI;
    int i = blockIdx.x * blockDim.x + threadIdx.x;
    if (i < n1) {
        __nv_bfloat16 h, l;
        split_bf16(in_w[i], h, l);
        g_wih[i] = h; g_wil[i] = l;
    } else if (i < n1 + n2) {
        int j = i - n1;
        int k = j % DI;
        int r = (j / DI) % 64;
        int lyr = j / (64 * DI);
        float v = (r < XD) ? xp[((size_t)lyr * XD + r) * DI + k] : 0.f;
        __nv_bfloat16 h, l;
        split_bf16(v, h, l);
        g_wxh[j] = h; g_wxl[j] = l;
    } else if (i < n1 + n2 + n3) {
        int j = i - n1 - n2;
        __nv_bfloat16 h, l;
        split_bf16(ow[j], h, l);
        g_woh[j] = h; g_wol[j] = l;
    }
}

// ---------------- embed: one block per token, 192 threads --------------------
__global__ void embed_kernel(const float* __restrict__ imgs,
                             const float* __restrict__ pw,
                             const float* __restrict__ pb,
                             const float* __restrict__ pos,
                             const float* __restrict__ clstok) {
    int t = blockIdx.x;
    int m = threadIdx.x;
    int b = t / LSEQ;
    int l = t - b * LSEQ;
    float v;
    if (l < 400) {
        const float* ip = imgs + b * 1600 + l * 4;
        v = pb[m]
          + ip[0] * pw[0*DM + m] + ip[1] * pw[1*DM + m]
          + ip[2] * pw[2*DM + m] + ip[3] * pw[3*DM + m]
          + pos[l*DM + m];
    } else {
        v = clstok[m] + pos[400*DM + m];
    }
    g_hidden[t*DM + m] = v;
}

// -------- residual add + rmsnorm (warp/token), emits bf16 hi/lo --------------
__global__ void add_rmsnorm_kernel(const float* __restrict__ nw, int first) {
    int warp = threadIdx.x >> 5, lane = threadIdx.x & 31;
    int t = blockIdx.x * 8 + warp;
    if (t >= NTOK) return;
    float v[6];
    float ss = 0.f;
#pragma unroll
    for (int i = 0; i < 6; i++) {
        int m = lane + i*32;
        float r = g_hidden[t*DM + m];
        if (!first) r += g_resid[t*DM + m];
        g_resid[t*DM + m] = r;
        v[i] = r;
        ss += r * r;
    }
#pragma unroll
    for (int o = 16; o; o >>= 1) ss += __shfl_xor_sync(0xffffffffu, ss, o);
    float s = rsqrtf(ss * (1.0f/192.0f) + 1e-5f);
#pragma unroll
    for (int i = 0; i < 6; i++) {
        int m = lane + i*32;
        float x = v[i] * s * nw[m];
        __nv_bfloat16 h, l;
        split_bf16(x, h, l);
        g_ah[t*DM + m] = h;
        g_al[t*DM + m] = l;
    }
}

// ------ depthwise causal conv (k=4) + SiLU: 4 tokens x 4 channels per thread --
#define NTG 101
__global__ void conv_silu_kernel(const float* __restrict__ cw,
                                 const float* __restrict__ cb) {
    int idx = blockIdx.x * blockDim.x + threadIdx.x;
    if (idx >= BATCH * NTG * (DI/4)) return;
    int d4  = idx % (DI/4);
    int rem = idx / (DI/4);
    int gr  = rem % NTG;
    int b   = rem / NTG;
    int l0  = gr * 4;
    int d   = d4 * 4;
    float4 w0 = *(const float4*)&cw[(d+0)*4];
    float4 w1 = *(const float4*)&cw[(d+1)*4];
    float4 w2 = *(const float4*)&cw[(d+2)*4];
    float4 w3 = *(const float4*)&cw[(d+3)*4];
    float4 bias = *(const float4*)&cb[d];

    float4 xb[7];
#pragma unroll
    for (int j = 0; j < 7; j++) {
        int l = l0 + j - 3;
        if (l >= 0 && l < LSEQ)
            xb[j] = *(const float4*)&g_xz[((size_t)b*LSEQ + l)*768 + d];
        else
            xb[j] = make_float4(0.f, 0.f, 0.f, 0.f);
    }
#pragma unroll
    for (int i = 0; i < 4; i++) {
        int l = l0 + i;
        if (l < LSEQ) {
            float4 acc = bias;
            acc.x += w0.x*xb[i].x + w0.y*xb[i+1].x + w0.z*xb[i+2].x + w0.w*xb[i+3].x;
            acc.y += w1.x*xb[i].y + w1.y*xb[i+1].y + w1.z*xb[i+2].y + w1.w*xb[i+3].y;
            acc.z += w2.x*xb[i].z + w2.y*xb[i+1].z + w2.z*xb[i+2].z + w2.w*xb[i+3].z;
            acc.w += w3.x*xb[i].w + w3.y*xb[i+1].w + w3.z*xb[i+2].w + w3.w*xb[i+3].w;
            float4 o;
            o.x = acc.x / (1.f + __expf(-acc.x));
            o.y = acc.y / (1.f + __expf(-acc.y));
            o.z = acc.z / (1.f + __expf(-acc.z));
            o.w = acc.w / (1.f + __expf(-acc.w));
            size_t t = (size_t)b*LSEQ + l;
            *(float4*)&g_uconv[t*DI + d] = o;
            __nv_bfloat16 h0,q0,h1,q1,h2,q2,h3,q3;
            split_bf16(o.x, h0, q0); split_bf16(o.y, h1, q1);
            split_bf16(o.z, h2, q2); split_bf16(o.w, h3, q3);
            __nv_bfloat162* ph = (__nv_bfloat162*)&g_uh[t*DI + d];
            __nv_bfloat162* pl = (__nv_bfloat162*)&g_ul[t*DI + d];
            ph[0] = __halves2bfloat162(h0, h1); ph[1] = __halves2bfloat162(h2, h3);
            pl[0] = __halves2bfloat162(q0, q1); pl[1] = __halves2bfloat162(q2, q3);
        }
    }
}

// -------------- dt projection + softplus (smem-tiled, 32 tokens/block) -------
__global__ void dt_kernel(const float* __restrict__ dtw,
                          const float* __restrict__ dtb) {
    __shared__ float dtw_s[DTR * DI];
    __shared__ float dtb_s[DI];
    __shared__ float xr_s[32 * DTR];
    int tid = threadIdx.x;              // 384
    int t0 = blockIdx.x * 32;
#pragma unroll
    for (int k = 0; k < DTR; k++) {
        int i = tid + k * DI;
        int d_ = i / DTR, r_ = i % DTR;
        dtw_s[r_ * DI + d_] = dtw[i];
    }
    dtb_s[tid] = dtb[tid];
    {
        int tok = tid / DTR, r = tid % DTR;
        if (tok < 32) xr_s[tok * DTR + r] = g_xdbl[(size_t)(t0 + tok) * XD + r];
    }
    __syncthreads();
    int d = tid;
    float w[DTR];
#pragma unroll
    for (int r = 0; r < DTR; r++) w[r] = dtw_s[r * DI + d];
    float bsv = dtb_s[d];
    for (int tok = 0; tok < 32; tok++) {
        float s = bsv;
#pragma unroll
        for (int r = 0; r < DTR; r++) s += xr_s[tok * DTR + r] * w[r];
        float sp = fmaxf(s, 0.f) + log1pf(__expf(-fabsf(s)));
        g_dt[(size_t)(t0 + tok) * DI + d] = sp;
    }
}

// ======================= chunked parallel selective scan =======================
__global__ void scan_p1(const float* __restrict__ A_log) {
    int b = blockIdx.x;
    int d = blockIdx.y * 128 + threadIdx.x;
    int c = blockIdx.z;
    int warp = threadIdx.x >> 5, lane = threadIdx.x & 31;
    __shared__ float bcs[4][3][16];
    float An[DS], h[DS];
#pragma unroll
    for (int n = 0; n < DS; n++) {
        An[n] = -expf(A_log[d*DS + n]);
        h[n] = 0.f;
    }
    bool structured = true;
#pragma unroll
    for (int n = 1; n < DS; n++)
        structured = structured &&
            (fabsf(An[n] - (float)(n+1)*An[0]) <= 1e-4f*fabsf(An[n]) + 1e-6f);

    int l0 = c * CL;
    int steps = CL;
    const float* xb  = g_xdbl  + ((size_t)b*LSEQ + l0)*XD + 12;
    const float* dtp = g_dt    + ((size_t)b*LSEQ + l0)*DI + d;
    const float* up  = g_uconv + ((size_t)b*LSEQ + l0)*DI + d;

    float bcr1 = 0.f, dt0, u0, dt1 = 0.f, u1 = 0.f;
    if (lane < 16) bcs[warp][0][lane] = xb[lane];
    dt0 = dtp[0]; u0 = up[0];
    if (steps > 1) {
        if (lane < 16) bcr1 = xb[XD + lane];
        dt1 = dtp[DI]; u1 = up[DI];
    }
    __syncwarp();

    float S = 0.f;
    for (int i = 0; i < steps; i++) {
        if (i + 1 < steps && lane < 16) bcs[warp][(i+1)%3][lane] = bcr1;
        float bcr2 = 0.f, dt2 = 0.f, u2 = 0.f;
        if (i + 2 < steps) {
            if (lane < 16) bcr2 = xb[(size_t)(i+2)*XD + lane];
            dt2 = dtp[(size_t)(i+2)*DI];
            u2  = up [(size_t)(i+2)*DI];
        }
        __syncwarp();
        const float* Bc = bcs[warp][i % 3];
        float dtv = dt0, uv = u0;
        float dtu = dtv * uv;
        S += dtv;
        if (structured) {
            float E = __expf(dtv * An[0]);
            float P = E;
#pragma unroll
            for (int n = 0; n < DS; n++) {
                h[n] = P * h[n] + dtu * Bc[n];
                P *= E;
            }
        } else {
#pragma unroll
            for (int n = 0; n < DS; n++) {
                float dA = __expf(dtv * An[n]);
                h[n] = dA * h[n] + dtu * Bc[n];
            }
        }
        dt0 = dt1; u0 = u1;
        dt1 = dt2; u1 = u2;
        bcr1 = bcr2;
    }

    size_t base = (((size_t)b*NCHUNK + c)*DI + d)*DS;
    float P[DS];
    if (structured) {
        float E = __expf(S * An[0]);
        float pp = E;
#pragma unroll
        for (int n = 0; n < DS; n++) { P[n] = pp; pp *= E; }
    } else {
#pragma unroll
        for (int n = 0; n < DS; n++) P[n] = __expf(S * An[n]);
    }
#pragma unroll
    for (int q = 0; q < 4; q++) {
        *(float4*)&g_scanF[base + q*4] = make_float4(h[q*4], h[q*4+1], h[q*4+2], h[q*4+3]);
        *(float4*)&g_scanP[base + q*4] = make_float4(P[q*4], P[q*4+1], P[q*4+2], P[q*4+3]);
    }
}

__global__ void scan_mid() {
    int b = blockIdx.x;
    int d = blockIdx.y * 128 + threadIdx.x;
    float H[DS];
#pragma unroll
    for (int n = 0; n < DS; n++) H[n] = 0.f;
    for (int c = 0; c < NCHUNK - 1; c++) {
        size_t base = (((size_t)b*NCHUNK + c)*DI + d)*DS;
#pragma unroll
        for (int q = 0; q < 4; q++) {
            float4 F = *(const float4*)&g_scanF[base + q*4];
            float4 P = *(const float4*)&g_scanP[base + q*4];
            H[q*4+0] = F.x + P.x * H[q*4+0];
            H[q*4+1] = F.y + P.y * H[q*4+1];
            H[q*4+2] = F.z + P.z * H[q*4+2];
            H[q*4+3] = F.w + P.w * H[q*4+3];
        }
        size_t ibase = (((size_t)b*NCHUNK + c + 1)*DI + d)*DS;
#pragma unroll
        for (int q = 0; q < 4; q++)
            *(float4*)&g_scanI[ibase + q*4] =
                make_float4(H[q*4], H[q*4+1], H[q*4+2], H[q*4+3]);
    }
}

__global__ void scan_p3(const float* __restrict__ A_log,
                        const float* __restrict__ Dv) {
    int b = blockIdx.x;
    int d = blockIdx.y * 128 + threadIdx.x;
    int c = blockIdx.z;
    int warp = threadIdx.x >> 5, lane = threadIdx.x & 31;
    __shared__ float bcs[4][3][32];
    float An[DS], h[DS];
#pragma unroll
    for (int n = 0; n < DS; n++) An[n] = -expf(A_log[d*DS + n]);
    bool structured = true;
#pragma unroll
    for (int n = 1; n < DS; n++)
        structured = structured &&
            (fabsf(An[n] - (float)(n+1)*An[0]) <= 1e-4f*fabsf(An[n]) + 1e-6f);

    if (c == 0) {
#pragma unroll
        for (int n = 0; n < DS; n++) h[n] = 0.f;
    } else {
        size_t ibase = (((size_t)b*NCHUNK + c)*DI + d)*DS;
#pragma unroll
        for (int q = 0; q < 4; q++) {
            float4 v = *(const float4*)&g_scanI[ibase + q*4];
            h[q*4+0] = v.x; h[q*4+1] = v.y; h[q*4+2] = v.z; h[q*4+3] = v.w;
        }
    }

    int l0 = c * CL;
    int le = min(LSEQ, l0 + CL);
    int steps = le - l0;
    float Dd = Dv[d];
    const float* xb  = g_xdbl  + ((size_t)b*LSEQ + l0)*XD + 12;
    const float* dtp = g_dt    + ((size_t)b*LSEQ + l0)*DI + d;
    const float* up  = g_uconv + ((size_t)b*LSEQ + l0)*DI + d;
    const float* zp  = g_xz    + ((size_t)b*LSEQ + l0)*768 + DI + d;
    __nv_bfloat16* yhp = g_yh + ((size_t)b*LSEQ + l0)*DI + d;
    __nv_bfloat16* ylp = g_yl + ((size_t)b*LSEQ + l0)*DI + d;

    float bcr1 = 0.f, dt0, u0, z0, dt1 = 0.f, u1 = 0.f, z1 = 0.f;
    bcs[warp][0][lane] = xb[lane];
    dt0 = dtp[0]; u0 = up[0]; z0 = zp[0];
    if (steps > 1) {
        bcr1 = xb[XD + lane];
        dt1 = dtp[DI]; u1 = up[DI]; z1 = zp[768];
    }
    __syncwarp();

    for (int i = 0; i < steps; i++) {
        if (i + 1 < steps) bcs[warp][(i+1)%3][lane] = bcr1;
        float bcr2 = 0.f, dt2 = 0.f, u2 = 0.f, z2 = 0.f;
        if (i + 2 < steps) {
            bcr2 = xb[(size_t)(i+2)*XD + lane];
            dt2  = dtp[(size_t)(i+2)*DI];
            u2   = up [(size_t)(i+2)*DI];
            z2   = zp [(size_t)(i+2)*768];
        }
        __syncwarp();
        const float* BCc = bcs[warp][i % 3];
        float dtv = dt0, uv = u0, zv = z0;
        float dtu = dtv * uv;
        float y = 0.f;
        if (structured) {
            float E = __expf(dtv * An[0]);
            float P = E;
#pragma unroll
            for (int n = 0; n < DS; n++) {
                h[n] = P * h[n] + dtu * BCc[n];
                y += h[n] * BCc[16 + n];
                P *= E;
            }
        } else {
#pragma unroll
            for (int n = 0; n < DS; n++) {
                float dA = __expf(dtv * An[n]);
                h[n] = dA * h[n] + dtu * BCc[n];
                y += h[n] * BCc[16 + n];
            }
        }
        y += uv * Dd;
        float sz = zv / (1.f + __expf(-zv));
        float yo = y * sz;
        __nv_bfloat16 hh, ll;
        split_bf16(yo, hh, ll);
        yhp[(size_t)i * DI] = hh;
        ylp[(size_t)i * DI] = ll;
        dt0 = dt1; u0 = u1; z0 = z1;
        dt1 = dt2; u1 = u2; z1 = z2;
        bcr1 = bcr2;
    }
}

// -------------- final norm on cls tokens only ---------------------------------
__global__ void final_norm_kernel(const float* __restrict__ normf) {
    int warp = threadIdx.x >> 5, lane = threadIdx.x & 31;
    int b = blockIdx.x * 8 + warp;
    if (b >= BATCH) return;
    int t = b * LSEQ + 400;
    float v[6];
    float ss = 0.f;
#pragma unroll
    for (int i = 0; i < 6; i++) {
        int m = lane + i*32;
        float r = g_hidden[t*DM + m] + g_resid[t*DM + m];
        v[i] = r;
        ss += r * r;
    }
#pragma unroll
    for (int o = 16; o; o >>= 1) ss += __shfl_xor_sync(0xffffffffu, ss, o);
    float s = rsqrtf(ss * (1.0f/192.0f) + 1e-5f);
#pragma unroll
    for (int i = 0; i < 6; i++) {
        int m = lane + i*32;
        g_cls[b*DM + m] = v[i] * s * normf[m];
    }
}

// -------------- FFMA2 GEMM (head only): C = A[M,K] * B[N,K]^T + bias ---------
template<int BN, int TN>
__global__ void __launch_bounds__(256, 2)
gemm_ffma2(const float* __restrict__ A,
           const float* __restrict__ Bw,
           const float* __restrict__ bias,
           float* __restrict__ C,
           int M, int N, int K) {
    constexpr int BM = 128, BK = 16;
    constexpr int NTX = BN / TN;
    __shared__ float As[BK][BM + 4];
    __shared__ float Bs[BK][BN + 4];
    int tid = threadIdx.x;
    int tx = tid % NTX, ty = tid / NTX;
    int row0 = blockIdx.y * BM, col0 = blockIdx.x * BN;
    unsigned long long acc[4][TN];
#pragma unroll
    for (int i = 0; i < 4; i++)
#pragma unroll
        for (int j = 0; j < TN; j++) acc[i][j] = 0ull;
    int lr  = tid >> 2;
    int lc4 = (tid & 3) * 4;
    for (int k0 = 0; k0 < K; k0 += BK) {
#pragma unroll
        for (int h = 0; h < 2; h++) {
            int rr = lr + h * 64;
            float4 v = make_float4(0.f, 0.f, 0.f, 0.f);
            if (row0 + rr < M)
                v = *(const float4*)&A[(size_t)(row0 + rr) * K + k0 + lc4];
            As[lc4+0][rr] = v.x; As[lc4+1][rr] = v.y;
            As[lc4+2][rr] = v.z; As[lc4+3][rr] = v.w;
        }
        constexpr int NB = (BN * BK) / (256 * 4);
#pragma unroll
        for (int h = 0; h < NB; h++) {
            int nn = lr + h * 64;
            float4 v = make_float4(0.f, 0.f, 0.f, 0.f);
            if (col0 + nn < N)
                v = *(const float4*)&Bw[(size_t)(col0 + nn) * K + k0 + lc4];
            Bs[lc4+0][nn] = v.x; Bs[lc4+1][nn] = v.y;
            Bs[lc4+2][nn] = v.z; Bs[lc4+3][nn] = v.w;
        }
        __syncthreads();
#pragma unroll
        for (int k = 0; k < BK; k++) {
            ulonglong2 a01 = *(const ulonglong2*)&As[k][ty * 8];
            ulonglong2 a23 = *(const ulonglong2*)&As[k][ty * 8 + 4];
            unsigned long long ap[4] = { a01.x, a01.y, a23.x, a23.y };
            unsigned long long bp[TN];
            float4 b0 = *(const float4*)&Bs[k][tx * TN];
            asm("mov.b64 %0, {%1, %1};" : "=l"(bp[0]) : "f"(b0.x));
            asm("mov.b64 %0, {%1, %1};" : "=l"(bp[1]) : "f"(b0.y));
            asm("mov.b64 %0, {%1, %1};" : "=l"(bp[2]) : "f"(b0.z));
            asm("mov.b64 %0, {%1, %1};" : "=l"(bp[3]) : "f"(b0.w));
            if (TN == 8) {
                float4 b1 = *(const float4*)&Bs[k][tx * TN + 4];
                asm("mov.b64 %0, {%1, %1};" : "=l"(bp[4]) : "f"(b1.x));
                asm("mov.b64 %0, {%1, %1};" : "=l"(bp[5]) : "f"(b1.y));
                asm("mov.b64 %0, {%1, %1};" : "=l"(bp[6]) : "f"(b1.z));
                asm("mov.b64 %0, {%1, %1};" : "=l"(bp[7]) : "f"(b1.w));
            }
#pragma unroll
            for (int i = 0; i < 4; i++)
#pragma unroll
                for (int j = 0; j < TN; j++)
                    asm("fma.rn.f32x2 %0, %1, %2, %0;"
                        : "+l"(acc[i][j]) : "l"(ap[i]), "l"(bp[j]));
        }
        __syncthreads();
    }
#pragma unroll
    for (int i = 0; i < 4; i++) {
        int r0 = row0 + ty * 8 + 2 * i;
#pragma unroll
        for (int j = 0; j < TN; j++) {
            int c = col0 + tx * TN + j;
            if (c < N) {
                float lo, hi;
                asm("mov.b64 {%0, %1}, %2;" : "=f"(lo), "=f"(hi) : "l"(acc[i][j]));
                float bv = bias ? bias[c] : 0.f;
                if (r0 < M)     C[(size_t)r0 * N + c]       = lo + bv;
                if (r0 + 1 < M) C[(size_t)(r0 + 1) * N + c] = hi + bv;
            }
        }
    }
}

// ==============================================================================
extern "C" void kernel_launch(void* const* d_in, const int* in_sizes, int n_in,
                              void* d_out, int out_size) {
    const float* imgs      = (const float*)d_in[0];
    const float* patch_w   = (const float*)d_in[1];
    const float* patch_b   = (const float*)d_in[2];
    const float* pos_embed = (const float*)d_in[3];
    const float* cls_token = (const float*)d_in[4];
    const float* norm_w    = (const float*)d_in[5];
    const float* in_proj_w = (const float*)d_in[6];
    const float* conv_w    = (const float*)d_in[7];
    const float* conv_b    = (const float*)d_in[8];
    const float* xproj_w   = (const float*)d_in[9];
    const float* dt_w      = (const float*)d_in[10];
    const float* dt_b      = (const float*)d_in[11];
    const float* A_log     = (const float*)d_in[12];
    const float* D_param   = (const float*)d_in[13];
    const float* out_w     = (const float*)d_in[14];
    const float* normf_w   = (const float*)d_in[15];
    const float* head_w    = (const float*)d_in[16];
    const float* head_b    = (const float*)d_in[17];
    float* out = (float*)d_out;

    float *p_xz, *p_xdbl, *p_hidden, *p_cls;
    cudaGetSymbolAddress((void**)&p_xz,     g_xz);
    cudaGetSymbolAddress((void**)&p_xdbl,   g_xdbl);
    cudaGetSymbolAddress((void**)&p_hidden, g_hidden);
    cudaGetSymbolAddress((void**)&p_cls,    g_cls);
    __nv_bfloat16 *p_ah, *p_al, *p_uh, *p_ul, *p_yh, *p_yl;
    __nv_bfloat16 *p_wih, *p_wil, *p_wxh, *p_wxl, *p_woh, *p_wol;
    cudaGetSymbolAddress((void**)&p_ah, g_ah);   cudaGetSymbolAddress((void**)&p_al, g_al);
    cudaGetSymbolAddress((void**)&p_uh, g_uh);   cudaGetSymbolAddress((void**)&p_ul, g_ul);
    cudaGetSymbolAddress((void**)&p_yh, g_yh);   cudaGetSymbolAddress((void**)&p_yl, g_yl);
    cudaGetSymbolAddress((void**)&p_wih, g_wih); cudaGetSymbolAddress((void**)&p_wil, g_wil);
    cudaGetSymbolAddress((void**)&p_wxh, g_wxh); cudaGetSymbolAddress((void**)&p_wxl, g_wxl);
    cudaGetSymbolAddress((void**)&p_woh, g_woh); cudaGetSymbolAddress((void**)&p_wol, g_wol);

    cudaFuncSetAttribute(gemm_mma, cudaFuncAttributeMaxDynamicSharedMemorySize,
                         GEMM_SMEM_BYTES);

    const int CVT_N = 4*768*DM + 4*64*DI + 4*DM*DI;
    cvt_all_kernel<<<(CVT_N + 255)/256, 256>>>(in_proj_w, xproj_w, out_w);

    embed_kernel<<<NTOK, DM>>>(imgs, patch_w, patch_b, pos_embed, cls_token);

    const int MT = (NTOK + 127) / 128;   // 101

    for (int i = 0; i < 4; i++) {
        add_rmsnorm_kernel<<<(NTOK + 7)/8, 256>>>(norm_w + i*DM, i == 0);

        gemm_mma<<<dim3(12, MT), 256, GEMM_SMEM_BYTES>>>(
            p_ah, p_al, p_wih + (size_t)i*768*DM, p_wil + (size_t)i*768*DM,
            p_xz, NTOK, 768, DM);

        conv_silu_kernel<<<(BATCH*NTG*(DI/4) + 255)/256, 256>>>(
            conv_w + i*DI*4, conv_b + i*DI);

        gemm_mma<<<dim3(1, MT), 256, GEMM_SMEM_BYTES>>>(
            p_uh, p_ul, p_wxh + (size_t)i*64*DI, p_wxl + (size_t)i*64*DI,
            p_xdbl, NTOK, XD, DI);

        dt_kernel<<<NTOK/32, 384>>>(dt_w + i*DI*DTR, dt_b + i*DI);

        scan_p1<<<dim3(BATCH, 3, NCHUNK-1), 128>>>(A_log + (size_t)i*DI*DS);
        scan_mid<<<dim3(BATCH, 3), 128>>>();
        scan_p3<<<dim3(BATCH, 3, NCHUNK), 128>>>(A_log + (size_t)i*DI*DS, D_param + i*DI);

        gemm_mma<<<dim3(3, MT), 256, GEMM_SMEM_BYTES>>>(
            p_yh, p_yl, p_woh + (size_t)i*DM*DI, p_wol + (size_t)i*DM*DI,
            p_hidden, NTOK, DM, DI);
    }

    final_norm_kernel<<<(BATCH + 7)/8, 256>>>(normf_w);

    gemm_ffma2<128,8><<<dim3((NCLS + 127)/128, 1), 256>>>(
        p_cls, head_w, head_b, out, BATCH, NCLS, DM);
}